// round 4
// baseline (speedup 1.0000x reference)
#include <cuda_runtime.h>
#include <math.h>

// ---------------- problem constants (fixed shapes) ----------------
#define N_PTS    160000
#define NL0      100000
#define NL1       60000
#define NG       128          // gt boxes
#define NC       128          // channels
#define GEMM_ROWS 128
#define GEMM_BLOCKS (N_PTS / GEMM_ROWS)   // 1250

// ---------------- device scratch (no allocation allowed) ----------------
__device__ float g_fused[(size_t)N_PTS * NC];       // 82 MB fused activations
__device__ float g_T4[4 * NC];                      // text @ W_fuse[128:] + b_fuse
__device__ float g_partial[NC * GEMM_BLOCKS];       // per-block channel sums
__device__ float g_partialsq[NC * GEMM_BLOCKS];     // per-block channel sumsq
__device__ __align__(16) float g_scale[NC];
__device__ __align__(16) float g_shift[NC];
__device__ float g_kth[NG];

// ---------------- packed f32x2 helpers (sm_103a FFMA2 path) ----------------
__device__ __forceinline__ unsigned long long pack2(float v) {
    unsigned long long r;
    asm("mov.b64 %0, {%1, %2};" : "=l"(r)
        : "r"(__float_as_uint(v)), "r"(__float_as_uint(v)));
    return r;
}
__device__ __forceinline__ void unpack2(unsigned long long p, float& lo, float& hi) {
    unsigned a, b;
    asm("mov.b64 {%0, %1}, %2;" : "=r"(a), "=r"(b) : "l"(p));
    lo = __uint_as_float(a); hi = __uint_as_float(b);
}
#define FMA2(d, a, b) asm("fma.rn.f32x2 %0, %1, %2, %0;" : "+l"(d) : "l"(a), "l"(b))

// =====================================================================
// Kernel 0: T4 = text_feats @ W_fuse[128:256] + b_fuse   (4 x 128, tiny)
// =====================================================================
__global__ void t4_kernel(const float* __restrict__ text,
                          const float* __restrict__ Wf,
                          const float* __restrict__ bfuse) {
    int t = threadIdx.x >> 7;      // 0..3
    int c = threadIdx.x & 127;     // 0..127
    float acc = bfuse[c];
    #pragma unroll 8
    for (int k = 0; k < 128; k++)
        acc = fmaf(text[t * 128 + k], Wf[(128 + k) * 128 + c], acc);
    g_T4[t * 128 + c] = acc;
}

// =====================================================================
// Kernel 1: fused = backbone @ W_fuse[:128] + T4[bidx]; also per-block
//           channel sum / sumsq partials. 128-row tiles, 8x8/thread,
//           packed f32x2 FMA.
// =====================================================================
__global__ void __launch_bounds__(256, 1)
gemm_kernel(const float* __restrict__ bf, const float* __restrict__ Wf,
            const int* __restrict__ bidx) {
    extern __shared__ float smem[];
    float* sW  = smem;                        // 128*128 = 16384 floats
    float* sX  = smem + 16384;                // 128*132 = 16896 floats (padded)
    float* sT4 = smem + 16384 + 16896;        // 512
    int*   sBi = (int*)(smem + 16384 + 16896 + 512);  // 128

    const int tid = threadIdx.x;
    const int tx = tid & 15;      // col group: cols [tx*8, tx*8+8)
    const int ty = tid >> 4;      // row group: rows [ty*8, ty*8+8)
    const int brow = blockIdx.x * GEMM_ROWS;

    // load W (top half of W_fuse, row-major 128x128)
    const float4* Wf4 = (const float4*)Wf;
    float4* sW4 = (float4*)sW;
    for (int i = tid; i < 4096; i += 256) sW4[i] = Wf4[i];
    // load X tile: 128 rows x 32 float4 into padded rows (stride 132 floats)
    const float4* bf4 = (const float4*)bf;
    for (int i = tid; i < 4096; i += 256) {
        int r = i >> 5, c4 = i & 31;
        *(float4*)&sX[r * 132 + c4 * 4] = bf4[(size_t)(brow + r) * 32 + c4];
    }
    for (int i = tid; i < 512; i += 256) sT4[i] = g_T4[i];   // FIX: was if(tid<512) with 256 threads
    if (tid < 128) sBi[tid] = bidx[brow + tid];
    __syncthreads();

    unsigned long long acc[8][4];   // 8 rows x 4 col-pairs (8 cols)
    #pragma unroll
    for (int i = 0; i < 8; i++)
        #pragma unroll
        for (int j = 0; j < 4; j++) acc[i][j] = 0ULL;

    #pragma unroll 4
    for (int k = 0; k < 128; k++) {
        unsigned long long xp[8];
        #pragma unroll
        for (int i = 0; i < 8; i++) xp[i] = pack2(sX[(ty * 8 + i) * 132 + k]);
        const ulonglong2* wr = (const ulonglong2*)&sW[k * 128 + tx * 8];
        ulonglong2 wA = wr[0], wB = wr[1];
        #pragma unroll
        for (int i = 0; i < 8; i++) {
            FMA2(acc[i][0], xp[i], wA.x);
            FMA2(acc[i][1], xp[i], wA.y);
            FMA2(acc[i][2], xp[i], wB.x);
            FMA2(acc[i][3], xp[i], wB.y);
        }
    }

    // epilogue: add T4[bidx], store fused, accumulate stats
    float ts[8], tq[8];
    #pragma unroll
    for (int j = 0; j < 8; j++) { ts[j] = 0.f; tq[j] = 0.f; }
    #pragma unroll
    for (int i = 0; i < 8; i++) {
        int rl = ty * 8 + i;
        int row = brow + rl;
        const float* t4 = &sT4[sBi[rl] * 128 + tx * 8];
        float f[8];
        #pragma unroll
        for (int j4 = 0; j4 < 4; j4++) unpack2(acc[i][j4], f[2 * j4], f[2 * j4 + 1]);
        #pragma unroll
        for (int j = 0; j < 8; j++) f[j] += t4[j];
        *(float4*)&g_fused[(size_t)row * 128 + tx * 8]     = make_float4(f[0], f[1], f[2], f[3]);
        *(float4*)&g_fused[(size_t)row * 128 + tx * 8 + 4] = make_float4(f[4], f[5], f[6], f[7]);
        #pragma unroll
        for (int j = 0; j < 8; j++) { ts[j] += f[j]; tq[j] += f[j] * f[j]; }
    }
    __syncthreads();   // done reading sW/sX — reuse sW as reduction buffer
    #pragma unroll
    for (int j = 0; j < 8; j++) {
        sW[(tx * 8 + j) * 16 + ty]        = ts[j];
        sW[2048 + (tx * 8 + j) * 16 + ty] = tq[j];
    }
    __syncthreads();
    if (tid < 128) {
        float s = 0.f, q = 0.f;
        #pragma unroll
        for (int t = 0; t < 16; t++) { s += sW[tid * 16 + t]; q += sW[2048 + tid * 16 + t]; }
        g_partial[tid * GEMM_BLOCKS + blockIdx.x]   = s;
        g_partialsq[tid * GEMM_BLOCKS + blockIdx.x] = q;
    }
}

// =====================================================================
// Kernel 2: reduce partials -> BN scale/shift per channel (deterministic)
// =====================================================================
__global__ void stats_kernel(const float* __restrict__ gamma,
                             const float* __restrict__ beta) {
    const int c = blockIdx.x;          // 128 blocks
    const int tid = threadIdx.x;       // 256 threads
    __shared__ float rs[256], rq[256];
    float s = 0.f, q = 0.f;
    for (int b = tid; b < GEMM_BLOCKS; b += 256) {
        s += g_partial[c * GEMM_BLOCKS + b];
        q += g_partialsq[c * GEMM_BLOCKS + b];
    }
    rs[tid] = s; rq[tid] = q;
    __syncthreads();
    for (int o = 128; o > 0; o >>= 1) {
        if (tid < o) { rs[tid] += rs[tid + o]; rq[tid] += rq[tid + o]; }
        __syncthreads();
    }
    if (tid == 0) {
        float mu  = rs[0] / (float)N_PTS;
        float var = rq[0] / (float)N_PTS - mu * mu;
        float sc  = gamma[c] * rsqrtf(var + 1e-5f);
        g_scale[c] = sc;
        g_shift[c] = beta[c] - mu * sc;
    }
}

// =====================================================================
// Kernel 3: x = relu(BN(fused)); preds = [reg0:3, exp(reg3:6), reg6, cls]
// =====================================================================
__global__ void __launch_bounds__(256)
head2_kernel(const float* __restrict__ Wb, const float* __restrict__ bb,
             const float* __restrict__ Wc, const float* __restrict__ bc,
             float* __restrict__ out) {
    __shared__ float4 sw[9][32];
    __shared__ float4 ssc[32], ssh[32];
    __shared__ float sb[9];
    const int tid = threadIdx.x;
    for (int i = tid; i < 288; i += 256) {   // FIX: was if(tid<288) with 256 threads
        int j = i >> 5, k4 = i & 31, k = k4 * 4;
        float4 w;
        if (j < 7) w = make_float4(Wb[(k+0)*7+j], Wb[(k+1)*7+j], Wb[(k+2)*7+j], Wb[(k+3)*7+j]);
        else { int jc = j - 7;
               w = make_float4(Wc[(k+0)*2+jc], Wc[(k+1)*2+jc], Wc[(k+2)*2+jc], Wc[(k+3)*2+jc]); }
        sw[j][k4] = w;
    }
    if (tid < 32) { ssc[tid] = ((const float4*)g_scale)[tid]; ssh[tid] = ((const float4*)g_shift)[tid]; }
    if (tid < 9) sb[tid] = (tid < 7) ? bb[tid] : bc[tid - 7];
    __syncthreads();

    const int p = blockIdx.x * 256 + tid;   // grid sized exactly
    float acc[9];
    #pragma unroll
    for (int j = 0; j < 9; j++) acc[j] = sb[j];
    const float4* gf = (const float4*)g_fused;
    #pragma unroll 4
    for (int k4 = 0; k4 < 32; k4++) {
        float4 f = gf[(size_t)p * 32 + k4];
        float4 sc = ssc[k4], sh = ssh[k4];
        float x0 = fmaxf(fmaf(f.x, sc.x, sh.x), 0.f);
        float x1 = fmaxf(fmaf(f.y, sc.y, sh.y), 0.f);
        float x2 = fmaxf(fmaf(f.z, sc.z, sh.z), 0.f);
        float x3 = fmaxf(fmaf(f.w, sc.w, sh.w), 0.f);
        #pragma unroll
        for (int j = 0; j < 9; j++) {
            float4 w = sw[j][k4];
            acc[j] = fmaf(x0, w.x, acc[j]);
            acc[j] = fmaf(x1, w.y, acc[j]);
            acc[j] = fmaf(x2, w.z, acc[j]);
            acc[j] = fmaf(x3, w.w, acc[j]);
        }
    }
    float* o = out + (size_t)p * 9;
    o[0] = acc[0]; o[1] = acc[1]; o[2] = acc[2];
    o[3] = expf(acc[3]); o[4] = expf(acc[4]); o[5] = expf(acc[5]);
    o[6] = acc[6]; o[7] = acc[7]; o[8] = acc[8];
}

// =====================================================================
// Kernel 4: exact 33rd-smallest masked d2 per gt (histogram select)
// =====================================================================
#define NBUCK 4096
#define BSCALE 235.0f
#define CANDMAX 2048
#define KSEL 33

__global__ void __launch_bounds__(512)
kth_kernel(const float* __restrict__ p0, const float* __restrict__ p1,
           const float* __restrict__ boxes, const int* __restrict__ labels) {
    const int g = blockIdx.x;
    const int tid = threadIdx.x;
    __shared__ unsigned hist[NBUCK];
    __shared__ unsigned csum[512];
    __shared__ float cand[CANDMAX];
    __shared__ int sInfo[3];   // [0]=bucket B  [1]=count below  [2]=cand count

    const int lvl = labels[g];                 // LABEL2LEVEL = (0,1) identity
    const float* pts = lvl ? p1 : p0;
    const int n = lvl ? NL1 : NL0;
    const float cx = boxes[g * 7 + 0], cy = boxes[g * 7 + 1], cz = boxes[g * 7 + 2];

    for (int i = tid; i < NBUCK; i += 512) hist[i] = 0u;
    if (tid == 0) sInfo[2] = 0;
    __syncthreads();

    for (int i = tid; i < n; i += 512) {
        float dx = pts[3 * i] - cx, dy = pts[3 * i + 1] - cy, dz = pts[3 * i + 2] - cz;
        float d2 = fmaf(dz, dz, fmaf(dy, dy, dx * dx));
        int b = (int)(sqrtf(d2) * BSCALE); b = b > (NBUCK - 1) ? (NBUCK - 1) : b;
        atomicAdd(&hist[b], 1u);
    }
    __syncthreads();

    unsigned cs = 0;
    #pragma unroll
    for (int i = 0; i < 8; i++) cs += hist[tid * 8 + i];
    csum[tid] = cs;
    __syncthreads();
    if (tid == 0) {
        unsigned run = 0; int chunk = 0;
        while (chunk < 512 && run + csum[chunk] < KSEL) { run += csum[chunk]; chunk++; }
        int B = chunk * 8;
        while (run + hist[B] < KSEL) { run += hist[B]; B++; }
        sInfo[0] = B; sInfo[1] = (int)run;
    }
    __syncthreads();
    const int B = sInfo[0];

    for (int i = tid; i < n; i += 512) {
        float dx = pts[3 * i] - cx, dy = pts[3 * i + 1] - cy, dz = pts[3 * i + 2] - cz;
        float d2 = fmaf(dz, dz, fmaf(dy, dy, dx * dx));
        int b = (int)(sqrtf(d2) * BSCALE); b = b > (NBUCK - 1) ? (NBUCK - 1) : b;
        if (b == B) {
            int pos = atomicAdd(&sInfo[2], 1);
            if (pos < CANDMAX) cand[pos] = d2;
        }
    }
    __syncthreads();
    if (tid == 0) {
        int m = sInfo[2]; if (m > CANDMAX) m = CANDMAX;
        int need = KSEL - sInfo[1];            // rank (1-indexed) within bucket B
        float kth = 1e8f;
        for (int r = 0; r < need; r++) {
            float best = 3.4e38f; int bi = 0;
            for (int i = 0; i < m; i++) { float v = cand[i]; if (v < best) { best = v; bi = i; } }
            kth = best; cand[bi] = 3.4e38f;
        }
        g_kth[g] = kth;
    }
}

// =====================================================================
// Kernel 5: per-point assignment
// =====================================================================
__global__ void __launch_bounds__(256)
assign_kernel(const float* __restrict__ p0, const float* __restrict__ p1,
              const float* __restrict__ boxes, const int* __restrict__ labels,
              float* __restrict__ out) {
    __shared__ float4 sc0[NG], sc1[NG];   // (cx,cy,cz, gated-threshold per point-level)
    const int tid = threadIdx.x;
    if (tid < NG) {
        float cx = boxes[tid * 7 + 0], cy = boxes[tid * 7 + 1], cz = boxes[tid * 7 + 2];
        int lvl = labels[tid];
        float kth = g_kth[tid];
        sc0[tid] = make_float4(cx, cy, cz, (lvl == 0) ? kth : -1.0f);
        sc1[tid] = make_float4(cx, cy, cz, (lvl == 1) ? kth : -1.0f);
    }
    __syncthreads();

    const int p = blockIdx.x * 256 + tid;   // grid sized exactly to N_PTS
    float px, py, pz; const float4* Cc;
    if (p < NL0) { px = p0[3 * p]; py = p0[3 * p + 1]; pz = p0[3 * p + 2]; Cc = sc0; }
    else { int q = p - NL0; px = p1[3 * q]; py = p1[3 * q + 1]; pz = p1[3 * q + 2]; Cc = sc1; }

    float best = 3.4e38f; int bi = 0;       // unmasked argmin (first occurrence)
    float gbest = 1e8f;   int gi = -1;      // gated argmin
    #pragma unroll 4
    for (int g = 0; g < NG; g++) {
        float4 c = Cc[g];
        float dx = px - c.x, dy = py - c.y, dz = pz - c.z;
        float d2 = fmaf(dz, dz, fmaf(dy, dy, dx * dx));
        if (d2 < best) { best = d2; bi = g; }
        if (d2 < c.w && d2 < gbest) { gbest = d2; gi = g; }
    }
    int a = (gi == bi) ? gi : -1;           // gi==-1 never equals bi>=0
    out[(size_t)N_PTS * 9 + p] = (float)a;
}

// =====================================================================
// launch
// =====================================================================
extern "C" void kernel_launch(void* const* d_in, const int* in_sizes, int n_in,
                              void* d_out, int out_size) {
    const float* bf    = (const float*)d_in[0];
    const float* text  = (const float*)d_in[1];
    const float* Wf    = (const float*)d_in[2];
    const float* bfu   = (const float*)d_in[3];
    const float* gamma = (const float*)d_in[4];
    const float* beta  = (const float*)d_in[5];
    const float* Wb    = (const float*)d_in[6];
    const float* bb    = (const float*)d_in[7];
    const float* Wc    = (const float*)d_in[8];
    const float* bc    = (const float*)d_in[9];
    const float* p0    = (const float*)d_in[10];
    const float* p1    = (const float*)d_in[11];
    // disambiguate metadata ordering at runtime: signature order puts gt_boxes
    // (128*7 = 896 elems) at index 12; setup_inputs dict order puts batch_idx there.
    const bool sig = (in_sizes[12] == 128 * 7);
    const float* boxes  = (const float*)d_in[sig ? 12 : 14];
    const int*   bidx   = (const int*)  d_in[sig ? 13 : 12];
    const int*   labels = (const int*)  d_in[sig ? 14 : 13];
    float* out = (float*)d_out;

    const size_t GEMM_SMEM = (16384 + 16896 + 512 + 128) * sizeof(float);
    cudaFuncSetAttribute(gemm_kernel, cudaFuncAttributeMaxDynamicSharedMemorySize,
                         (int)GEMM_SMEM);

    // assignment path (independent of head path)
    kth_kernel<<<NG, 512>>>(p0, p1, boxes, labels);
    assign_kernel<<<N_PTS / 256, 256>>>(p0, p1, boxes, labels, out);

    // head path
    t4_kernel<<<1, 512>>>(text, Wf, bfu);
    gemm_kernel<<<GEMM_BLOCKS, 256, GEMM_SMEM>>>(bf, Wf, bidx);
    stats_kernel<<<128, 256>>>(gamma, beta);
    head2_kernel<<<N_PTS / 256, 256>>>(Wb, bb, Wc, bc, out);
}

// round 5
// speedup vs baseline: 1.4164x; 1.4164x over previous
#include <cuda_runtime.h>
#include <math.h>

// ---------------- problem constants (fixed shapes) ----------------
#define N_PTS    160000
#define NL0      100000
#define NL1       60000
#define NG       128          // gt boxes
#define NC       128          // channels
#define GEMM_ROWS 256
#define GEMM_BLOCKS (N_PTS / GEMM_ROWS)   // 625

// ---------------- device scratch (no allocation allowed) ----------------
__device__ float g_fused[(size_t)N_PTS * NC];       // 82 MB fused activations
__device__ float g_T4[4 * NC];                      // text @ W_fuse[128:] + b_fuse
__device__ float g_partial[NC * GEMM_BLOCKS];       // per-block channel sums
__device__ float g_partialsq[NC * GEMM_BLOCKS];     // per-block channel sumsq
__device__ __align__(16) float g_scale[NC];
__device__ __align__(16) float g_shift[NC];
__device__ float g_kth[NG];

#define CAND_CAP 2048
__device__ float g_cand[(size_t)NG * CAND_CAP];     // per-gt candidate d2 values
__device__ int   g_cnt[NG];                         // per-gt candidate counts

#define R2_L0 1.44f   // level-0: density 100/u^3 -> corner-gt expected ~90 >= 33
#define R2_L1 2.25f   // level-1: density  60/u^3 -> corner-gt expected ~106 >= 33

// ---------------- packed f32x2 helpers (sm_103a FFMA2 path) ----------------
__device__ __forceinline__ unsigned long long pack2(float v) {
    unsigned long long r;
    asm("mov.b64 %0, {%1, %2};" : "=l"(r)
        : "r"(__float_as_uint(v)), "r"(__float_as_uint(v)));
    return r;
}
__device__ __forceinline__ void unpack2(unsigned long long p, float& lo, float& hi) {
    unsigned a, b;
    asm("mov.b64 {%0, %1}, %2;" : "=r"(a), "=r"(b) : "l"(p));
    lo = __uint_as_float(a); hi = __uint_as_float(b);
}
#define FMA2(d, a, b) asm("fma.rn.f32x2 %0, %1, %2, %0;" : "+l"(d) : "l"(a), "l"(b))

// =====================================================================
// Kernel 0: T4 = text_feats @ W_fuse[128:256] + b_fuse   (4 x 128, tiny)
// =====================================================================
__global__ void t4_kernel(const float* __restrict__ text,
                          const float* __restrict__ Wf,
                          const float* __restrict__ bfuse) {
    int t = threadIdx.x >> 7;      // 0..3
    int c = threadIdx.x & 127;     // 0..127
    float acc = bfuse[c];
    #pragma unroll 8
    for (int k = 0; k < 128; k++)
        acc = fmaf(text[t * 128 + k], Wf[(128 + k) * 128 + c], acc);
    g_T4[t * 128 + c] = acc;
}

// =====================================================================
// Kernel 1: fused = backbone @ W_fuse[:128] + T4[bidx]; also per-block
//           channel sum / sumsq partials. 256-row tiles, 512 threads
//           (16 warps/SM for latency hiding), 8x8/thread, f32x2 FMA.
// =====================================================================
__global__ void __launch_bounds__(512, 1)
gemm_kernel(const float* __restrict__ bf, const float* __restrict__ Wf,
            const int* __restrict__ bidx) {
    extern __shared__ float smem[];
    float* sW  = smem;                        // 128*128 = 16384 floats
    float* sX  = smem + 16384;                // 256*132 = 33792 floats (padded)
    float* sT4 = smem + 16384 + 33792;        // 512
    int*   sBi = (int*)(smem + 16384 + 33792 + 512);  // 256

    const int tid = threadIdx.x;
    const int tx = tid & 15;      // col group: cols [tx*8, tx*8+8)
    const int ty = tid >> 4;      // row group 0..31: rows [ty*8, ty*8+8)
    const int brow = blockIdx.x * GEMM_ROWS;

    // load W (top half of W_fuse, row-major 128x128)
    const float4* Wf4 = (const float4*)Wf;
    float4* sW4 = (float4*)sW;
    for (int i = tid; i < 4096; i += 512) sW4[i] = Wf4[i];
    // load X tile: 256 rows x 32 float4 into padded rows (stride 132 floats)
    const float4* bf4 = (const float4*)bf;
    for (int i = tid; i < 8192; i += 512) {
        int r = i >> 5, c4 = i & 31;
        *(float4*)&sX[r * 132 + c4 * 4] = bf4[(size_t)(brow + r) * 32 + c4];
    }
    sT4[tid] = g_T4[tid];
    if (tid < 256) sBi[tid] = bidx[brow + tid];
    __syncthreads();

    unsigned long long acc[8][4];   // 8 rows x 4 col-pairs (8 cols)
    #pragma unroll
    for (int i = 0; i < 8; i++)
        #pragma unroll
        for (int j = 0; j < 4; j++) acc[i][j] = 0ULL;

    #pragma unroll 4
    for (int k = 0; k < 128; k++) {
        unsigned long long xp[8];
        #pragma unroll
        for (int i = 0; i < 8; i++) xp[i] = pack2(sX[(ty * 8 + i) * 132 + k]);
        const ulonglong2* wr = (const ulonglong2*)&sW[k * 128 + tx * 8];
        ulonglong2 wA = wr[0], wB = wr[1];
        #pragma unroll
        for (int i = 0; i < 8; i++) {
            FMA2(acc[i][0], xp[i], wA.x);
            FMA2(acc[i][1], xp[i], wA.y);
            FMA2(acc[i][2], xp[i], wB.x);
            FMA2(acc[i][3], xp[i], wB.y);
        }
    }

    // epilogue: add T4[bidx], store fused, accumulate stats
    float ts[8], tq[8];
    #pragma unroll
    for (int j = 0; j < 8; j++) { ts[j] = 0.f; tq[j] = 0.f; }
    #pragma unroll
    for (int i = 0; i < 8; i++) {
        int rl = ty * 8 + i;
        int row = brow + rl;
        const float* t4 = &sT4[sBi[rl] * 128 + tx * 8];
        float f[8];
        #pragma unroll
        for (int j4 = 0; j4 < 4; j4++) unpack2(acc[i][j4], f[2 * j4], f[2 * j4 + 1]);
        #pragma unroll
        for (int j = 0; j < 8; j++) f[j] += t4[j];
        *(float4*)&g_fused[(size_t)row * 128 + tx * 8]     = make_float4(f[0], f[1], f[2], f[3]);
        *(float4*)&g_fused[(size_t)row * 128 + tx * 8 + 4] = make_float4(f[4], f[5], f[6], f[7]);
        #pragma unroll
        for (int j = 0; j < 8; j++) { ts[j] += f[j]; tq[j] += f[j] * f[j]; }
    }
    __syncthreads();   // done reading sW/sX — reuse sW as reduction buffer
    // channel c = tx*8+j (0..127), 32 ty groups; stride 33 avoids bank conflicts
    #pragma unroll
    for (int j = 0; j < 8; j++) {
        sW[(tx * 8 + j) * 33 + ty]        = ts[j];
        sW[4224 + (tx * 8 + j) * 33 + ty] = tq[j];
    }
    __syncthreads();
    if (tid < 128) {
        float s = 0.f, q = 0.f;
        #pragma unroll
        for (int t = 0; t < 32; t++) { s += sW[tid * 33 + t]; q += sW[4224 + tid * 33 + t]; }
        g_partial[tid * GEMM_BLOCKS + blockIdx.x]   = s;
        g_partialsq[tid * GEMM_BLOCKS + blockIdx.x] = q;
    }
}

// =====================================================================
// Kernel 2: reduce partials -> BN scale/shift per channel (deterministic)
// =====================================================================
__global__ void stats_kernel(const float* __restrict__ gamma,
                             const float* __restrict__ beta) {
    const int c = blockIdx.x;          // 128 blocks
    const int tid = threadIdx.x;       // 256 threads
    __shared__ float rs[256], rq[256];
    float s = 0.f, q = 0.f;
    for (int b = tid; b < GEMM_BLOCKS; b += 256) {
        s += g_partial[c * GEMM_BLOCKS + b];
        q += g_partialsq[c * GEMM_BLOCKS + b];
    }
    rs[tid] = s; rq[tid] = q;
    __syncthreads();
    for (int o = 128; o > 0; o >>= 1) {
        if (tid < o) { rs[tid] += rs[tid + o]; rq[tid] += rq[tid + o]; }
        __syncthreads();
    }
    if (tid == 0) {
        float mu  = rs[0] / (float)N_PTS;
        float var = rq[0] / (float)N_PTS - mu * mu;
        float sc  = gamma[c] * rsqrtf(var + 1e-5f);
        g_scale[c] = sc;
        g_shift[c] = beta[c] - mu * sc;
    }
}

// =====================================================================
// Kernel 3: x = relu(BN(fused)); preds = [reg0:3, exp(reg3:6), reg6, cls]
// =====================================================================
__global__ void __launch_bounds__(256)
head2_kernel(const float* __restrict__ Wb, const float* __restrict__ bb,
             const float* __restrict__ Wc, const float* __restrict__ bc,
             float* __restrict__ out) {
    __shared__ float4 sw[9][32];
    __shared__ float4 ssc[32], ssh[32];
    __shared__ float sb[9];
    const int tid = threadIdx.x;
    for (int i = tid; i < 288; i += 256) {
        int j = i >> 5, k4 = i & 31, k = k4 * 4;
        float4 w;
        if (j < 7) w = make_float4(Wb[(k+0)*7+j], Wb[(k+1)*7+j], Wb[(k+2)*7+j], Wb[(k+3)*7+j]);
        else { int jc = j - 7;
               w = make_float4(Wc[(k+0)*2+jc], Wc[(k+1)*2+jc], Wc[(k+2)*2+jc], Wc[(k+3)*2+jc]); }
        sw[j][k4] = w;
    }
    if (tid < 32) { ssc[tid] = ((const float4*)g_scale)[tid]; ssh[tid] = ((const float4*)g_shift)[tid]; }
    if (tid < 9) sb[tid] = (tid < 7) ? bb[tid] : bc[tid - 7];
    __syncthreads();

    const int p = blockIdx.x * 256 + tid;   // grid sized exactly
    float acc[9];
    #pragma unroll
    for (int j = 0; j < 9; j++) acc[j] = sb[j];
    const float4* gf = (const float4*)g_fused;
    #pragma unroll 4
    for (int k4 = 0; k4 < 32; k4++) {
        float4 f = gf[(size_t)p * 32 + k4];
        float4 sc = ssc[k4], sh = ssh[k4];
        float x0 = fmaxf(fmaf(f.x, sc.x, sh.x), 0.f);
        float x1 = fmaxf(fmaf(f.y, sc.y, sh.y), 0.f);
        float x2 = fmaxf(fmaf(f.z, sc.z, sh.z), 0.f);
        float x3 = fmaxf(fmaf(f.w, sc.w, sh.w), 0.f);
        #pragma unroll
        for (int j = 0; j < 9; j++) {
            float4 w = sw[j][k4];
            acc[j] = fmaf(x0, w.x, acc[j]);
            acc[j] = fmaf(x1, w.y, acc[j]);
            acc[j] = fmaf(x2, w.z, acc[j]);
            acc[j] = fmaf(x3, w.w, acc[j]);
        }
    }
    float* o = out + (size_t)p * 9;
    o[0] = acc[0]; o[1] = acc[1]; o[2] = acc[2];
    o[3] = expf(acc[3]); o[4] = expf(acc[4]); o[5] = expf(acc[5]);
    o[6] = acc[6]; o[7] = acc[7]; o[8] = acc[8];
}

// =====================================================================
// Kernel 4a: zero candidate counters
// =====================================================================
__global__ void zero_cnt_kernel() { g_cnt[threadIdx.x] = 0; }

// =====================================================================
// Kernel 4b: candidate collection — one pass over all points x 128 gts,
//            append d2 < r^2(level) to per-gt global lists.
// =====================================================================
__global__ void __launch_bounds__(256)
cand_kernel(const float* __restrict__ p0, const float* __restrict__ p1,
            const float* __restrict__ boxes, const int* __restrict__ labels) {
    __shared__ float4 sc0[NG], sc1[NG];   // (cx,cy,cz, r2-if-level-matches else -1)
    const int tid = threadIdx.x;
    if (tid < NG) {
        float cx = boxes[tid * 7 + 0], cy = boxes[tid * 7 + 1], cz = boxes[tid * 7 + 2];
        int lvl = labels[tid];
        sc0[tid] = make_float4(cx, cy, cz, (lvl == 0) ? R2_L0 : -1.0f);
        sc1[tid] = make_float4(cx, cy, cz, (lvl == 1) ? R2_L1 : -1.0f);
    }
    __syncthreads();

    const int p = blockIdx.x * 256 + tid;
    float px, py, pz; const float4* Cc;
    if (p < NL0) { px = p0[3 * p]; py = p0[3 * p + 1]; pz = p0[3 * p + 2]; Cc = sc0; }
    else { int q = p - NL0; px = p1[3 * q]; py = p1[3 * q + 1]; pz = p1[3 * q + 2]; Cc = sc1; }

    #pragma unroll 4
    for (int g = 0; g < NG; g++) {
        float4 c = Cc[g];
        float dx = px - c.x, dy = py - c.y, dz = pz - c.z;
        float d2 = fmaf(dz, dz, fmaf(dy, dy, dx * dx));   // SAME chain as assign
        if (d2 < c.w) {
            int idx = atomicAdd(&g_cnt[g], 1);
            if (idx < CAND_CAP) g_cand[(size_t)g * CAND_CAP + idx] = d2;
        }
    }
}

// =====================================================================
// Kernel 4c: exact 33rd-smallest per gt. Normal path: histogram-select
//            over the candidate list. Fallback (cnt<33 or overflow):
//            histogram-select over the full point set.
// =====================================================================
#define NBUCK 4096
#define BSCALE 235.0f
#define BCANDMAX 2048
#define KSEL 33

__global__ void __launch_bounds__(512)
select_kernel(const float* __restrict__ p0, const float* __restrict__ p1,
              const float* __restrict__ boxes, const int* __restrict__ labels) {
    const int g = blockIdx.x;
    const int tid = threadIdx.x;
    __shared__ unsigned hist[NBUCK];
    __shared__ unsigned csum[512];
    __shared__ float bcand[BCANDMAX];
    __shared__ int sInfo[3];

    const int lvl = labels[g];
    const float* pts = lvl ? p1 : p0;
    const int n = lvl ? NL1 : NL0;
    const float cx = boxes[g * 7 + 0], cy = boxes[g * 7 + 1], cz = boxes[g * 7 + 2];

    const int cnt = g_cnt[g];
    const bool ok = (cnt >= KSEL && cnt <= CAND_CAP);
    const float* src = &g_cand[(size_t)g * CAND_CAP];
    const int m = ok ? cnt : n;

    for (int i = tid; i < NBUCK; i += 512) hist[i] = 0u;
    if (tid == 0) sInfo[2] = 0;
    __syncthreads();

    for (int i = tid; i < m; i += 512) {
        float d2;
        if (ok) d2 = src[i];
        else {
            float dx = pts[3 * i] - cx, dy = pts[3 * i + 1] - cy, dz = pts[3 * i + 2] - cz;
            d2 = fmaf(dz, dz, fmaf(dy, dy, dx * dx));
        }
        int b = (int)(sqrtf(d2) * BSCALE); b = b > (NBUCK - 1) ? (NBUCK - 1) : b;
        atomicAdd(&hist[b], 1u);
    }
    __syncthreads();

    unsigned cs = 0;
    #pragma unroll
    for (int i = 0; i < 8; i++) cs += hist[tid * 8 + i];
    csum[tid] = cs;
    __syncthreads();
    if (tid == 0) {
        unsigned run = 0; int chunk = 0;
        while (chunk < 512 && run + csum[chunk] < KSEL) { run += csum[chunk]; chunk++; }
        int B = chunk * 8;
        while (run + hist[B] < KSEL) { run += hist[B]; B++; }
        sInfo[0] = B; sInfo[1] = (int)run;
    }
    __syncthreads();
    const int B = sInfo[0];

    for (int i = tid; i < m; i += 512) {
        float d2;
        if (ok) d2 = src[i];
        else {
            float dx = pts[3 * i] - cx, dy = pts[3 * i + 1] - cy, dz = pts[3 * i + 2] - cz;
            d2 = fmaf(dz, dz, fmaf(dy, dy, dx * dx));
        }
        int b = (int)(sqrtf(d2) * BSCALE); b = b > (NBUCK - 1) ? (NBUCK - 1) : b;
        if (b == B) {
            int pos = atomicAdd(&sInfo[2], 1);
            if (pos < BCANDMAX) bcand[pos] = d2;
        }
    }
    __syncthreads();
    if (tid == 0) {
        int mb = sInfo[2]; if (mb > BCANDMAX) mb = BCANDMAX;
        int need = KSEL - sInfo[1];
        float kth = 1e8f;
        for (int r = 0; r < need; r++) {
            float best = 3.4e38f; int bi = 0;
            for (int i = 0; i < mb; i++) { float v = bcand[i]; if (v < best) { best = v; bi = i; } }
            kth = best; bcand[bi] = 3.4e38f;
        }
        g_kth[g] = kth;
    }
}

// =====================================================================
// Kernel 5: per-point assignment
// =====================================================================
__global__ void __launch_bounds__(256)
assign_kernel(const float* __restrict__ p0, const float* __restrict__ p1,
              const float* __restrict__ boxes, const int* __restrict__ labels,
              float* __restrict__ out) {
    __shared__ float4 sc0[NG], sc1[NG];   // (cx,cy,cz, gated-threshold per point-level)
    const int tid = threadIdx.x;
    if (tid < NG) {
        float cx = boxes[tid * 7 + 0], cy = boxes[tid * 7 + 1], cz = boxes[tid * 7 + 2];
        int lvl = labels[tid];
        float kth = g_kth[tid];
        sc0[tid] = make_float4(cx, cy, cz, (lvl == 0) ? kth : -1.0f);
        sc1[tid] = make_float4(cx, cy, cz, (lvl == 1) ? kth : -1.0f);
    }
    __syncthreads();

    const int p = blockIdx.x * 256 + tid;
    float px, py, pz; const float4* Cc;
    if (p < NL0) { px = p0[3 * p]; py = p0[3 * p + 1]; pz = p0[3 * p + 2]; Cc = sc0; }
    else { int q = p - NL0; px = p1[3 * q]; py = p1[3 * q + 1]; pz = p1[3 * q + 2]; Cc = sc1; }

    float best = 3.4e38f; int bi = 0;       // unmasked argmin (first occurrence)
    float gbest = 1e8f;   int gi = -1;      // gated argmin
    #pragma unroll 4
    for (int g = 0; g < NG; g++) {
        float4 c = Cc[g];
        float dx = px - c.x, dy = py - c.y, dz = pz - c.z;
        float d2 = fmaf(dz, dz, fmaf(dy, dy, dx * dx));
        if (d2 < best) { best = d2; bi = g; }
        if (d2 < c.w && d2 < gbest) { gbest = d2; gi = g; }
    }
    int a = (gi == bi) ? gi : -1;
    out[(size_t)N_PTS * 9 + p] = (float)a;
}

// =====================================================================
// launch
// =====================================================================
extern "C" void kernel_launch(void* const* d_in, const int* in_sizes, int n_in,
                              void* d_out, int out_size) {
    const float* bf    = (const float*)d_in[0];
    const float* text  = (const float*)d_in[1];
    const float* Wf    = (const float*)d_in[2];
    const float* bfu   = (const float*)d_in[3];
    const float* gamma = (const float*)d_in[4];
    const float* beta  = (const float*)d_in[5];
    const float* Wb    = (const float*)d_in[6];
    const float* bb    = (const float*)d_in[7];
    const float* Wc    = (const float*)d_in[8];
    const float* bc    = (const float*)d_in[9];
    const float* p0    = (const float*)d_in[10];
    const float* p1    = (const float*)d_in[11];
    const bool sig = (in_sizes[12] == 128 * 7);
    const float* boxes  = (const float*)d_in[sig ? 12 : 14];
    const int*   bidx   = (const int*)  d_in[sig ? 13 : 12];
    const int*   labels = (const int*)  d_in[sig ? 14 : 13];
    float* out = (float*)d_out;

    const size_t GEMM_SMEM = (16384 + 33792 + 512 + 256) * sizeof(float);  // ~199 KB
    cudaFuncSetAttribute(gemm_kernel, cudaFuncAttributeMaxDynamicSharedMemorySize,
                         (int)GEMM_SMEM);

    // assignment path
    zero_cnt_kernel<<<1, NG>>>();
    cand_kernel<<<N_PTS / 256, 256>>>(p0, p1, boxes, labels);
    select_kernel<<<NG, 512>>>(p0, p1, boxes, labels);
    assign_kernel<<<N_PTS / 256, 256>>>(p0, p1, boxes, labels, out);

    // head path
    t4_kernel<<<1, 512>>>(text, Wf, bfu);
    gemm_kernel<<<GEMM_BLOCKS, 512, GEMM_SMEM>>>(bf, Wf, bidx);
    stats_kernel<<<128, 256>>>(gamma, beta);
    head2_kernel<<<N_PTS / 256, 256>>>(Wb, bb, Wc, bc, out);
}

// round 7
// speedup vs baseline: 1.4432x; 1.0190x over previous
#include <cuda_runtime.h>
#include <math.h>

// ---------------- problem constants (fixed shapes) ----------------
#define N_PTS    160000
#define NL0      100000
#define NL1       60000
#define NG       128          // gt boxes
#define NC       128          // channels
#define GEMM_ROWS 256
#define GEMM_BLOCKS (N_PTS / GEMM_ROWS)   // 625

// ---------------- device scratch (no allocation allowed) ----------------
__device__ float g_fused[(size_t)N_PTS * NC];       // 82 MB fused activations
__device__ float g_T4[4 * NC];                      // text @ W_fuse[128:] + b_fuse
__device__ float g_partial[NC * GEMM_BLOCKS];       // per-block channel sums
__device__ float g_partialsq[NC * GEMM_BLOCKS];     // per-block channel sumsq
__device__ __align__(16) float g_scale[NC];
__device__ __align__(16) float g_shift[NC];
__device__ float g_kth[NG];

#define CAND_CAP 2048
__device__ float g_cand[(size_t)NG * CAND_CAP];     // per-gt candidate d2 values
__device__ int   g_cnt[NG];                         // per-gt candidate counts

#define R2_L0 1.44f   // level-0: density 100/u^3 -> corner-gt expected ~90 >= 33
#define R2_L1 2.25f   // level-1: density  60/u^3 -> corner-gt expected ~106 >= 33

// ---------------- packed f32x2 helpers (sm_103a FFMA2 path) ----------------
__device__ __forceinline__ unsigned long long pack2(float v) {
    unsigned long long r;
    asm("mov.b64 %0, {%1, %2};" : "=l"(r)
        : "r"(__float_as_uint(v)), "r"(__float_as_uint(v)));
    return r;
}
__device__ __forceinline__ void unpack2(unsigned long long p, float& lo, float& hi) {
    unsigned a, b;
    asm("mov.b64 {%0, %1}, %2;" : "=r"(a), "=r"(b) : "l"(p));
    lo = __uint_as_float(a); hi = __uint_as_float(b);
}
#define FMA2(d, a, b) asm("fma.rn.f32x2 %0, %1, %2, %0;" : "+l"(d) : "l"(a), "l"(b))

// =====================================================================
// Kernel 0: T4 = text_feats @ W_fuse[128:256] + b_fuse   (4 x 128, tiny)
// =====================================================================
__global__ void t4_kernel(const float* __restrict__ text,
                          const float* __restrict__ Wf,
                          const float* __restrict__ bfuse) {
    int t = threadIdx.x >> 7;      // 0..3
    int c = threadIdx.x & 127;     // 0..127
    float acc = bfuse[c];
    #pragma unroll 8
    for (int k = 0; k < 128; k++)
        acc = fmaf(text[t * 128 + k], Wf[(128 + k) * 128 + c], acc);
    g_T4[t * 128 + c] = acc;
}

// =====================================================================
// Kernel 1: fused = backbone @ W_fuse[:128] + T4[bidx]; also per-block
//           channel sum / sumsq partials. 256-row tiles, 512 threads,
//           8x8/thread, f32x2 FMA, X reads vectorized over k (LDS.128)
//           to keep smem-crossbar demand below the FMA-pipe demand.
// =====================================================================
__global__ void __launch_bounds__(512, 1)
gemm_kernel(const float* __restrict__ bf, const float* __restrict__ Wf,
            const int* __restrict__ bidx) {
    extern __shared__ float smem[];
    float* sW  = smem;                        // 128*128 = 16384 floats
    float* sX  = smem + 16384;                // 256*132 = 33792 floats (padded)
    float* sT4 = smem + 16384 + 33792;        // 512
    int*   sBi = (int*)(smem + 16384 + 33792 + 512);  // 256

    const int tid = threadIdx.x;
    const int tx = tid & 15;      // col group: cols [tx*8, tx*8+8)
    const int ty = tid >> 4;      // row group 0..31: rows [ty*8, ty*8+8)
    const int brow = blockIdx.x * GEMM_ROWS;

    // load W (top half of W_fuse, row-major 128x128)
    const float4* Wf4 = (const float4*)Wf;
    float4* sW4 = (float4*)sW;
    for (int i = tid; i < 4096; i += 512) sW4[i] = Wf4[i];
    // load X tile: 256 rows x 32 float4 into padded rows (stride 132 floats)
    const float4* bf4 = (const float4*)bf;
    for (int i = tid; i < 8192; i += 512) {
        int r = i >> 5, c4 = i & 31;
        *(float4*)&sX[r * 132 + c4 * 4] = bf4[(size_t)(brow + r) * 32 + c4];
    }
    sT4[tid] = g_T4[tid];
    if (tid < 256) sBi[tid] = bidx[brow + tid];
    __syncthreads();

    unsigned long long acc[8][4];   // 8 rows x 4 col-pairs (8 cols)
    #pragma unroll
    for (int i = 0; i < 8; i++)
        #pragma unroll
        for (int j = 0; j < 4; j++) acc[i][j] = 0ULL;

    // k loop in quads: one LDS.128 per row per 4 k-values (8 wf/warp/4k for X
    // instead of 32), W stays 2x LDS.128 per k. FMA pipe becomes the limiter.
    #pragma unroll 4
    for (int k4 = 0; k4 < 128; k4 += 4) {
        float4 xq[8];
        #pragma unroll
        for (int i = 0; i < 8; i++)
            xq[i] = *(const float4*)&sX[(ty * 8 + i) * 132 + k4];
        #pragma unroll
        for (int kk = 0; kk < 4; kk++) {
            const ulonglong2* wr = (const ulonglong2*)&sW[(k4 + kk) * 128 + tx * 8];
            ulonglong2 wA = wr[0], wB = wr[1];
            #pragma unroll
            for (int i = 0; i < 8; i++) {
                float xv = (kk == 0) ? xq[i].x : (kk == 1) ? xq[i].y
                         : (kk == 2) ? xq[i].z : xq[i].w;
                unsigned long long xp = pack2(xv);
                FMA2(acc[i][0], xp, wA.x);
                FMA2(acc[i][1], xp, wA.y);
                FMA2(acc[i][2], xp, wB.x);
                FMA2(acc[i][3], xp, wB.y);
            }
        }
    }

    // epilogue: add T4[bidx], store fused, accumulate stats
    float ts[8], tq[8];
    #pragma unroll
    for (int j = 0; j < 8; j++) { ts[j] = 0.f; tq[j] = 0.f; }
    #pragma unroll
    for (int i = 0; i < 8; i++) {
        int rl = ty * 8 + i;
        int row = brow + rl;
        const float* t4 = &sT4[sBi[rl] * 128 + tx * 8];
        float f[8];
        #pragma unroll
        for (int j4 = 0; j4 < 4; j4++) unpack2(acc[i][j4], f[2 * j4], f[2 * j4 + 1]);
        #pragma unroll
        for (int j = 0; j < 8; j++) f[j] += t4[j];
        *(float4*)&g_fused[(size_t)row * 128 + tx * 8]     = make_float4(f[0], f[1], f[2], f[3]);
        *(float4*)&g_fused[(size_t)row * 128 + tx * 8 + 4] = make_float4(f[4], f[5], f[6], f[7]);
        #pragma unroll
        for (int j = 0; j < 8; j++) { ts[j] += f[j]; tq[j] += f[j] * f[j]; }
    }
    __syncthreads();   // done reading sW/sX — reuse sW as reduction buffer
    // channel c = tx*8+j (0..127), 32 ty groups; stride 33 avoids bank conflicts
    #pragma unroll
    for (int j = 0; j < 8; j++) {
        sW[(tx * 8 + j) * 33 + ty]        = ts[j];
        sW[4224 + (tx * 8 + j) * 33 + ty] = tq[j];
    }
    __syncthreads();
    if (tid < 128) {
        float s = 0.f, q = 0.f;
        #pragma unroll
        for (int t = 0; t < 32; t++) { s += sW[tid * 33 + t]; q += sW[4224 + tid * 33 + t]; }
        g_partial[tid * GEMM_BLOCKS + blockIdx.x]   = s;
        g_partialsq[tid * GEMM_BLOCKS + blockIdx.x] = q;
    }
}

// =====================================================================
// Kernel 2: reduce partials -> BN scale/shift per channel (deterministic)
// =====================================================================
__global__ void stats_kernel(const float* __restrict__ gamma,
                             const float* __restrict__ beta) {
    const int c = blockIdx.x;          // 128 blocks
    const int tid = threadIdx.x;       // 256 threads
    __shared__ float rs[256], rq[256];
    float s = 0.f, q = 0.f;
    for (int b = tid; b < GEMM_BLOCKS; b += 256) {
        s += g_partial[c * GEMM_BLOCKS + b];
        q += g_partialsq[c * GEMM_BLOCKS + b];
    }
    rs[tid] = s; rq[tid] = q;
    __syncthreads();
    for (int o = 128; o > 0; o >>= 1) {
        if (tid < o) { rs[tid] += rs[tid + o]; rq[tid] += rq[tid + o]; }
        __syncthreads();
    }
    if (tid == 0) {
        float mu  = rs[0] / (float)N_PTS;
        float var = rq[0] / (float)N_PTS - mu * mu;
        float sc  = gamma[c] * rsqrtf(var + 1e-5f);
        g_scale[c] = sc;
        g_shift[c] = beta[c] - mu * sc;
    }
}

// =====================================================================
// Kernel 3: x = relu(BN(fused)); preds = [reg0:3, exp(reg3:6), reg6, cls]
// =====================================================================
__global__ void __launch_bounds__(256)
head2_kernel(const float* __restrict__ Wb, const float* __restrict__ bb,
             const float* __restrict__ Wc, const float* __restrict__ bc,
             float* __restrict__ out) {
    __shared__ float4 sw[9][32];
    __shared__ float4 ssc[32], ssh[32];
    __shared__ float sb[9];
    const int tid = threadIdx.x;
    for (int i = tid; i < 288; i += 256) {
        int j = i >> 5, k4 = i & 31, k = k4 * 4;
        float4 w;
        if (j < 7) w = make_float4(Wb[(k+0)*7+j], Wb[(k+1)*7+j], Wb[(k+2)*7+j], Wb[(k+3)*7+j]);
        else { int jc = j - 7;
               w = make_float4(Wc[(k+0)*2+jc], Wc[(k+1)*2+jc], Wc[(k+2)*2+jc], Wc[(k+3)*2+jc]); }
        sw[j][k4] = w;
    }
    if (tid < 32) { ssc[tid] = ((const float4*)g_scale)[tid]; ssh[tid] = ((const float4*)g_shift)[tid]; }
    if (tid < 9) sb[tid] = (tid < 7) ? bb[tid] : bc[tid - 7];
    __syncthreads();

    const int p = blockIdx.x * 256 + tid;   // grid sized exactly
    float acc[9];
    #pragma unroll
    for (int j = 0; j < 9; j++) acc[j] = sb[j];
    const float4* gf = (const float4*)g_fused;
    #pragma unroll 4
    for (int k4 = 0; k4 < 32; k4++) {
        float4 f = gf[(size_t)p * 32 + k4];
        float4 sc = ssc[k4], sh = ssh[k4];
        float x0 = fmaxf(fmaf(f.x, sc.x, sh.x), 0.f);
        float x1 = fmaxf(fmaf(f.y, sc.y, sh.y), 0.f);
        float x2 = fmaxf(fmaf(f.z, sc.z, sh.z), 0.f);
        float x3 = fmaxf(fmaf(f.w, sc.w, sh.w), 0.f);
        #pragma unroll
        for (int j = 0; j < 9; j++) {
            float4 w = sw[j][k4];
            acc[j] = fmaf(x0, w.x, acc[j]);
            acc[j] = fmaf(x1, w.y, acc[j]);
            acc[j] = fmaf(x2, w.z, acc[j]);
            acc[j] = fmaf(x3, w.w, acc[j]);
        }
    }
    float* o = out + (size_t)p * 9;
    o[0] = acc[0]; o[1] = acc[1]; o[2] = acc[2];
    o[3] = expf(acc[3]); o[4] = expf(acc[4]); o[5] = expf(acc[5]);
    o[6] = acc[6]; o[7] = acc[7]; o[8] = acc[8];
}

// =====================================================================
// Kernel 4a: zero candidate counters
// =====================================================================
__global__ void zero_cnt_kernel() { g_cnt[threadIdx.x] = 0; }

// =====================================================================
// Kernel 4b: candidate collection — one pass over all points x 128 gts,
//            append d2 < r^2(level) to per-gt global lists.
// =====================================================================
__global__ void __launch_bounds__(256)
cand_kernel(const float* __restrict__ p0, const float* __restrict__ p1,
            const float* __restrict__ boxes, const int* __restrict__ labels) {
    __shared__ float4 sc0[NG], sc1[NG];   // (cx,cy,cz, r2-if-level-matches else -1)
    const int tid = threadIdx.x;
    if (tid < NG) {
        float cx = boxes[tid * 7 + 0], cy = boxes[tid * 7 + 1], cz = boxes[tid * 7 + 2];
        int lvl = labels[tid];
        sc0[tid] = make_float4(cx, cy, cz, (lvl == 0) ? R2_L0 : -1.0f);
        sc1[tid] = make_float4(cx, cy, cz, (lvl == 1) ? R2_L1 : -1.0f);
    }
    __syncthreads();

    const int p = blockIdx.x * 256 + tid;
    float px, py, pz; const float4* Cc;
    if (p < NL0) { px = p0[3 * p]; py = p0[3 * p + 1]; pz = p0[3 * p + 2]; Cc = sc0; }
    else { int q = p - NL0; px = p1[3 * q]; py = p1[3 * q + 1]; pz = p1[3 * q + 2]; Cc = sc1; }

    #pragma unroll 4
    for (int g = 0; g < NG; g++) {
        float4 c = Cc[g];
        float dx = px - c.x, dy = py - c.y, dz = pz - c.z;
        float d2 = fmaf(dz, dz, fmaf(dy, dy, dx * dx));   // SAME chain as assign
        if (d2 < c.w) {
            int idx = atomicAdd(&g_cnt[g], 1);
            if (idx < CAND_CAP) g_cand[(size_t)g * CAND_CAP + idx] = d2;
        }
    }
}

// =====================================================================
// Kernel 4c: exact 33rd-smallest per gt. Normal path: histogram-select
//            over the candidate list. Fallback (cnt<33 or overflow):
//            histogram-select over the full point set.
// =====================================================================
#define NBUCK 4096
#define BSCALE 235.0f
#define BCANDMAX 2048
#define KSEL 33

__global__ void __launch_bounds__(512)
select_kernel(const float* __restrict__ p0, const float* __restrict__ p1,
              const float* __restrict__ boxes, const int* __restrict__ labels) {
    const int g = blockIdx.x;
    const int tid = threadIdx.x;
    __shared__ unsigned hist[NBUCK];
    __shared__ unsigned csum[512];
    __shared__ float bcand[BCANDMAX];
    __shared__ int sInfo[3];

    const int lvl = labels[g];
    const float* pts = lvl ? p1 : p0;
    const int n = lvl ? NL1 : NL0;
    const float cx = boxes[g * 7 + 0], cy = boxes[g * 7 + 1], cz = boxes[g * 7 + 2];

    const int cnt = g_cnt[g];
    const bool ok = (cnt >= KSEL && cnt <= CAND_CAP);
    const float* src = &g_cand[(size_t)g * CAND_CAP];
    const int m = ok ? cnt : n;

    for (int i = tid; i < NBUCK; i += 512) hist[i] = 0u;
    if (tid == 0) sInfo[2] = 0;
    __syncthreads();

    for (int i = tid; i < m; i += 512) {
        float d2;
        if (ok) d2 = src[i];
        else {
            float dx = pts[3 * i] - cx, dy = pts[3 * i + 1] - cy, dz = pts[3 * i + 2] - cz;
            d2 = fmaf(dz, dz, fmaf(dy, dy, dx * dx));
        }
        int b = (int)(sqrtf(d2) * BSCALE); b = b > (NBUCK - 1) ? (NBUCK - 1) : b;
        atomicAdd(&hist[b], 1u);
    }
    __syncthreads();

    unsigned cs = 0;
    #pragma unroll
    for (int i = 0; i < 8; i++) cs += hist[tid * 8 + i];
    csum[tid] = cs;
    __syncthreads();
    if (tid == 0) {
        unsigned run = 0; int chunk = 0;
        while (chunk < 512 && run + csum[chunk] < KSEL) { run += csum[chunk]; chunk++; }
        int B = chunk * 8;
        while (run + hist[B] < KSEL) { run += hist[B]; B++; }
        sInfo[0] = B; sInfo[1] = (int)run;
    }
    __syncthreads();
    const int B = sInfo[0];

    for (int i = tid; i < m; i += 512) {
        float d2;
        if (ok) d2 = src[i];
        else {
            float dx = pts[3 * i] - cx, dy = pts[3 * i + 1] - cy, dz = pts[3 * i + 2] - cz;
            d2 = fmaf(dz, dz, fmaf(dy, dy, dx * dx));
        }
        int b = (int)(sqrtf(d2) * BSCALE); b = b > (NBUCK - 1) ? (NBUCK - 1) : b;
        if (b == B) {
            int pos = atomicAdd(&sInfo[2], 1);
            if (pos < BCANDMAX) bcand[pos] = d2;
        }
    }
    __syncthreads();
    if (tid == 0) {
        int mb = sInfo[2]; if (mb > BCANDMAX) mb = BCANDMAX;
        int need = KSEL - sInfo[1];
        float kth = 1e8f;
        for (int r = 0; r < need; r++) {
            float best = 3.4e38f; int bi = 0;
            for (int i = 0; i < mb; i++) { float v = bcand[i]; if (v < best) { best = v; bi = i; } }
            kth = best; bcand[bi] = 3.4e38f;
        }
        g_kth[g] = kth;
    }
}

// =====================================================================
// Kernel 5: per-point assignment
// =====================================================================
__global__ void __launch_bounds__(256)
assign_kernel(const float* __restrict__ p0, const float* __restrict__ p1,
              const float* __restrict__ boxes, const int* __restrict__ labels,
              float* __restrict__ out) {
    __shared__ float4 sc0[NG], sc1[NG];   // (cx,cy,cz, gated-threshold per point-level)
    const int tid = threadIdx.x;
    if (tid < NG) {
        float cx = boxes[tid * 7 + 0], cy = boxes[tid * 7 + 1], cz = boxes[tid * 7 + 2];
        int lvl = labels[tid];
        float kth = g_kth[tid];
        sc0[tid] = make_float4(cx, cy, cz, (lvl == 0) ? kth : -1.0f);
        sc1[tid] = make_float4(cx, cy, cz, (lvl == 1) ? kth : -1.0f);
    }
    __syncthreads();

    const int p = blockIdx.x * 256 + tid;
    float px, py, pz; const float4* Cc;
    if (p < NL0) { px = p0[3 * p]; py = p0[3 * p + 1]; pz = p0[3 * p + 2]; Cc = sc0; }
    else { int q = p - NL0; px = p1[3 * q]; py = p1[3 * q + 1]; pz = p1[3 * q + 2]; Cc = sc1; }

    float best = 3.4e38f; int bi = 0;       // unmasked argmin (first occurrence)
    float gbest = 1e8f;   int gi = -1;      // gated argmin
    #pragma unroll 4
    for (int g = 0; g < NG; g++) {
        float4 c = Cc[g];
        float dx = px - c.x, dy = py - c.y, dz = pz - c.z;
        float d2 = fmaf(dz, dz, fmaf(dy, dy, dx * dx));
        if (d2 < best) { best = d2; bi = g; }
        if (d2 < c.w && d2 < gbest) { gbest = d2; gi = g; }
    }
    int a = (gi == bi) ? gi : -1;
    out[(size_t)N_PTS * 9 + p] = (float)a;
}

// =====================================================================
// launch
// =====================================================================
extern "C" void kernel_launch(void* const* d_in, const int* in_sizes, int n_in,
                              void* d_out, int out_size) {
    const float* bf    = (const float*)d_in[0];
    const float* text  = (const float*)d_in[1];
    const float* Wf    = (const float*)d_in[2];
    const float* bfu   = (const float*)d_in[3];
    const float* gamma = (const float*)d_in[4];
    const float* beta  = (const float*)d_in[5];
    const float* Wb    = (const float*)d_in[6];
    const float* bb    = (const float*)d_in[7];
    const float* Wc    = (const float*)d_in[8];
    const float* bc    = (const float*)d_in[9];
    const float* p0    = (const float*)d_in[10];
    const float* p1    = (const float*)d_in[11];
    const bool sig = (in_sizes[12] == 128 * 7);
    const float* boxes  = (const float*)d_in[sig ? 12 : 14];
    const int*   bidx   = (const int*)  d_in[sig ? 13 : 12];
    const int*   labels = (const int*)  d_in[sig ? 14 : 13];
    float* out = (float*)d_out;

    const size_t GEMM_SMEM = (16384 + 33792 + 512 + 256) * sizeof(float);  // ~199 KB
    cudaFuncSetAttribute(gemm_kernel, cudaFuncAttributeMaxDynamicSharedMemorySize,
                         (int)GEMM_SMEM);

    // assignment path
    zero_cnt_kernel<<<1, NG>>>();
    cand_kernel<<<N_PTS / 256, 256>>>(p0, p1, boxes, labels);
    select_kernel<<<NG, 512>>>(p0, p1, boxes, labels);
    assign_kernel<<<N_PTS / 256, 256>>>(p0, p1, boxes, labels, out);

    // head path
    t4_kernel<<<1, 512>>>(text, Wf, bfu);
    gemm_kernel<<<GEMM_BLOCKS, 512, GEMM_SMEM>>>(bf, Wf, bidx);
    stats_kernel<<<128, 256>>>(gamma, beta);
    head2_kernel<<<N_PTS / 256, 256>>>(Wb, bb, Wc, bc, out);
}